// round 15
// baseline (speedup 1.0000x reference)
#include <cuda_runtime.h>
#include <cuda_bf16.h>
#include <math.h>
#include <cstdint>

// Problem constants
#define NN    50000
#define EE    800000
#define ET    (EE + NN)      // edges + self loops
#define FIN   128
#define HIDC  128
#define HEADS 4
#define GG    512
#define C1    (HEADS * HIDC) // 512

// ---------------- scratch (static device globals; no allocation allowed) ---
__device__ __nv_bfloat16 g_h1b[(size_t)NN * C1];   // x @ W1 (bf16, gather src)
__device__ __nv_bfloat16 g_h2b[(size_t)NN * HIDC]; // act1 @ W2 (bf16)
__device__ __nv_bfloat16 g_xh[(size_t)NN * FIN];   // x (bf16)
__device__ __nv_bfloat16 g_a1h[(size_t)NN * C1];   // act1 (bf16)
__device__ __nv_bfloat16 g_w1h[C1 * FIN];    // W1^T [512][128] hi
__device__ __nv_bfloat16 g_w1l[C1 * FIN];    // W1^T lo
__device__ __nv_bfloat16 g_w2h[HIDC * C1];   // W2^T [128][512] hi
__device__ __nv_bfloat16 g_w2l[HIDC * C1];   // W2^T lo
__device__ float g_asrc1[NN * HEADS];
__device__ float g_adst1[NN * HEADS];
__device__ float g_asrc2[NN];
__device__ float g_adst2[NN];
__device__ int   g_deg[NN];
__device__ int   g_rowbeg[NN];
__device__ int   g_cursor[NN];
__device__ int   g_total;
__device__ int   g_esrc[ET];
__device__ float g_pool[GG * HIDC];
__device__ float g_cnt[GG];

// ====================== helpers ============================================
__device__ __forceinline__ void split_bf16(float v, __nv_bfloat16& h, __nv_bfloat16& l) {
    h = __float2bfloat16_rn(v);
    l = __float2bfloat16_rn(v - __bfloat162float(h));
}

// ---------------- fused init + conversions ---------------------------------
__global__ void prep_kernel(const float* __restrict__ X,
                            const float* __restrict__ W1,
                            const float* __restrict__ W2) {
    int i0 = blockIdx.x * blockDim.x + threadIdx.x;
    int stride = gridDim.x * blockDim.x;
    if (i0 == 0) g_total = 0;
    for (int k = i0; k < NN; k += stride) { g_deg[k] = 1; g_cursor[k] = 0; }
    for (int k = i0; k < GG * HIDC; k += stride) g_pool[k] = 0.f;
    for (int k = i0; k < GG; k += stride) g_cnt[k] = 0.f;
    for (int k = i0; k < NN * FIN / 4; k += stride) {
        int i = k * 4;
        float4 v = *reinterpret_cast<const float4*>(&X[i]);
        __nv_bfloat16 h[4];
        h[0] = __float2bfloat16_rn(v.x); h[1] = __float2bfloat16_rn(v.y);
        h[2] = __float2bfloat16_rn(v.z); h[3] = __float2bfloat16_rn(v.w);
        *reinterpret_cast<uint2*>(&g_xh[i]) = *reinterpret_cast<uint2*>(h);
    }
    for (int k = i0; k < FIN * C1; k += stride) {
        int kk = k / C1, n = k % C1;
        __nv_bfloat16 h, l;
        split_bf16(W1[k], h, l);
        g_w1h[n * FIN + kk] = h;
        g_w1l[n * FIN + kk] = l;
    }
    for (int k = i0; k < C1 * HIDC; k += stride) {
        int kk = k / HIDC, n = k % HIDC;
        __nv_bfloat16 h, l;
        split_bf16(W2[k], h, l);
        g_w2h[n * C1 + kk] = h;
        g_w2l[n * C1 + kk] = l;
    }
}

// ---------------- degree count ---------------------------------------------
__global__ void count_kernel(const int* __restrict__ ei) {
    int i = blockIdx.x * blockDim.x + threadIdx.x;
    if (i < EE) atomicAdd(&g_deg[ei[EE + i]], 1);
}

// ---------------- segment allocation (warp-aggregated atomics) -------------
// Each node gets a contiguous region [rowbeg, rowbeg + deg). Placement order
// is atomic-order nondeterministic; contents per node are unchanged.
__global__ void alloc_kernel() {
    int i = blockIdx.x * blockDim.x + threadIdx.x;
    int lane = threadIdx.x & 31;
    int d = (i < NN) ? g_deg[i] : 0;
    int sc = d;
#pragma unroll
    for (int o = 1; o < 32; o <<= 1) {
        int v = __shfl_up_sync(0xffffffffu, sc, o);
        if (lane >= o) sc += v;
    }
    int total = __shfl_sync(0xffffffffu, sc, 31);
    int base = 0;
    if (lane == 31) base = atomicAdd(&g_total, total);
    base = __shfl_sync(0xffffffffu, base, 31);
    if (i < NN) g_rowbeg[i] = base + sc - d;
}

// ---------------- scatter into CSR (edges + self loops) --------------------
__global__ void scatter_kernel(const int* __restrict__ ei) {
    int i = blockIdx.x * blockDim.x + threadIdx.x;
    if (i < EE) {
        int s = ei[i];
        int d = ei[EE + i];
        int pos = g_rowbeg[d] + atomicAdd(&g_cursor[d], 1);
        g_esrc[pos] = s;
    } else if (i < ET) {
        int n = i - EE;
        int pos = g_rowbeg[n] + atomicAdd(&g_cursor[n], 1);
        g_esrc[pos] = n;
    }
}

// ====================== bf16 mma.sync GEMM + fused dots ====================
// C = A @ B with A bf16 (activations), B bf16 hi/lo (weights).
// 2 accumulating MMAs per product: A*Bh + A*Bl.
#define KC     32
#define APAD   40

__device__ __forceinline__ void mma16816(float* c, const uint32_t* a, const uint32_t* b) {
    asm volatile(
        "mma.sync.aligned.m16n8k16.row.col.f32.bf16.bf16.f32 "
        "{%0,%1,%2,%3}, {%4,%5,%6,%7}, {%8,%9}, {%0,%1,%2,%3};"
        : "+f"(c[0]), "+f"(c[1]), "+f"(c[2]), "+f"(c[3])
        : "r"(a[0]), "r"(a[1]), "r"(a[2]), "r"(a[3]), "r"(b[0]), "r"(b[1]));
}

__global__ __launch_bounds__(256) void mma_gemm_kernel(
    const __nv_bfloat16* __restrict__ Ah,
    const __nv_bfloat16* __restrict__ Bth, const __nv_bfloat16* __restrict__ Btl,
    __nv_bfloat16* __restrict__ Cb,
    const float* __restrict__ avs, const float* __restrict__ avd,
    float* __restrict__ asrc_out, float* __restrict__ adst_out,
    int M, int Nn, int K, int H)
{
    __shared__ unsigned short Ahs[128 * APAD];
    __shared__ unsigned short Bhs[128 * APAD];
    __shared__ unsigned short Bls[128 * APAD];
    __shared__ float s_dt[2][128][2];

    int tid = threadIdx.x;
    int wid = tid >> 5, lane = tid & 31;
    int warp_m = wid & 3;
    int warp_n = wid >> 2;
    int g = lane >> 2, tg = lane & 3;
    int rowBase = blockIdx.y * 128;
    int colBase = blockIdx.x * 128;
    int head = blockIdx.x;

    float acc[2][8][4];
#pragma unroll
    for (int mt = 0; mt < 2; mt++)
#pragma unroll
        for (int nt = 0; nt < 8; nt++)
#pragma unroll
            for (int j = 0; j < 4; j++) acc[mt][nt][j] = 0.f;

    for (int k0 = 0; k0 < K; k0 += KC) {
#pragma unroll
        for (int l = 0; l < 4; l++) {
            int idx = tid + l * 256;          // 0..1023
            int row = idx >> 3;
            int q = idx & 7;
            int gr = rowBase + row;
            uint2 vh = make_uint2(0u, 0u);
            if (gr < M)
                vh = *reinterpret_cast<const uint2*>(&Ah[(size_t)gr * K + k0 + q * 4]);
            *reinterpret_cast<uint2*>(&Ahs[row * APAD + q * 4]) = vh;
        }
#pragma unroll
        for (int l = 0; l < 4; l++) {
            int idx = tid + l * 256;
            int n = idx >> 3;
            int q = idx & 7;
            uint2 vh = *reinterpret_cast<const uint2*>(&Bth[(size_t)(colBase + n) * K + k0 + q * 4]);
            uint2 vl = *reinterpret_cast<const uint2*>(&Btl[(size_t)(colBase + n) * K + k0 + q * 4]);
            *reinterpret_cast<uint2*>(&Bhs[n * APAD + q * 4]) = vh;
            *reinterpret_cast<uint2*>(&Bls[n * APAD + q * 4]) = vl;
        }
        __syncthreads();

#pragma unroll
        for (int ks = 0; ks < 2; ks++) {
            int kk = ks * 16;
            uint32_t afh[2][4];
#pragma unroll
            for (int mt = 0; mt < 2; mt++) {
                int r0 = (warp_m * 32 + mt * 16 + g) * APAD + kk + tg * 2;
                int r8 = r0 + 8 * APAD;
                afh[mt][0] = *reinterpret_cast<uint32_t*>(&Ahs[r0]);
                afh[mt][1] = *reinterpret_cast<uint32_t*>(&Ahs[r8]);
                afh[mt][2] = *reinterpret_cast<uint32_t*>(&Ahs[r0 + 8]);
                afh[mt][3] = *reinterpret_cast<uint32_t*>(&Ahs[r8 + 8]);
            }
#pragma unroll
            for (int nt = 0; nt < 8; nt++) {
                int nb = (warp_n * 64 + nt * 8 + g) * APAD + kk + tg * 2;
                uint32_t bfh[2], bfl[2];
                bfh[0] = *reinterpret_cast<uint32_t*>(&Bhs[nb]);
                bfh[1] = *reinterpret_cast<uint32_t*>(&Bhs[nb + 8]);
                bfl[0] = *reinterpret_cast<uint32_t*>(&Bls[nb]);
                bfl[1] = *reinterpret_cast<uint32_t*>(&Bls[nb + 8]);
#pragma unroll
                for (int mt = 0; mt < 2; mt++) {
                    mma16816(acc[mt][nt], afh[mt], bfh);
                    mma16816(acc[mt][nt], afh[mt], bfl);
                }
            }
        }
        __syncthreads();
    }

    // ---- epilogue: bf16 store + fused attention dots ----
    float ps[2][2] = {{0.f, 0.f}, {0.f, 0.f}};
    float pd[2][2] = {{0.f, 0.f}, {0.f, 0.f}};
#pragma unroll
    for (int nt = 0; nt < 8; nt++) {
        int c0 = colBase + warp_n * 64 + nt * 8 + tg * 2;
        float as0 = avs[c0], as1 = avs[c0 + 1];
        float ad0 = avd[c0], ad1 = avd[c0 + 1];
#pragma unroll
        for (int mt = 0; mt < 2; mt++) {
            int r0 = rowBase + warp_m * 32 + mt * 16 + g;
            __nv_bfloat162 v01 = __floats2bfloat162_rn(acc[mt][nt][0], acc[mt][nt][1]);
            __nv_bfloat162 v23 = __floats2bfloat162_rn(acc[mt][nt][2], acc[mt][nt][3]);
            if (r0 < M)
                *reinterpret_cast<__nv_bfloat162*>(&Cb[(size_t)r0 * Nn + c0]) = v01;
            if (r0 + 8 < M)
                *reinterpret_cast<__nv_bfloat162*>(&Cb[(size_t)(r0 + 8) * Nn + c0]) = v23;
            ps[mt][0] += acc[mt][nt][0] * as0 + acc[mt][nt][1] * as1;
            pd[mt][0] += acc[mt][nt][0] * ad0 + acc[mt][nt][1] * ad1;
            ps[mt][1] += acc[mt][nt][2] * as0 + acc[mt][nt][3] * as1;
            pd[mt][1] += acc[mt][nt][2] * ad0 + acc[mt][nt][3] * ad1;
        }
    }
#pragma unroll
    for (int mt = 0; mt < 2; mt++)
#pragma unroll
        for (int hf = 0; hf < 2; hf++) {
            ps[mt][hf] += __shfl_xor_sync(0xffffffffu, ps[mt][hf], 1);
            ps[mt][hf] += __shfl_xor_sync(0xffffffffu, ps[mt][hf], 2);
            pd[mt][hf] += __shfl_xor_sync(0xffffffffu, pd[mt][hf], 1);
            pd[mt][hf] += __shfl_xor_sync(0xffffffffu, pd[mt][hf], 2);
        }
    if (tg == 0) {
#pragma unroll
        for (int mt = 0; mt < 2; mt++)
#pragma unroll
            for (int hf = 0; hf < 2; hf++) {
                int lr = warp_m * 32 + mt * 16 + g + hf * 8;
                s_dt[0][lr][warp_n] = ps[mt][hf];
                s_dt[1][lr][warp_n] = pd[mt][hf];
            }
    }
    __syncthreads();
    if (tid < 128) {
        int grow = rowBase + tid;
        if (grow < M) {
            asrc_out[grow * H + head] = s_dt[0][tid][0] + s_dt[0][tid][1];
            adst_out[grow * H + head] = s_dt[1][tid][0] + s_dt[1][tid][1];
        }
    }
}

// ---------------- agg layer 1: H=4, uint4 gather (8 ch/thread) -------------
__global__ __launch_bounds__(128) void agg1_kernel(
    const __nv_bfloat16* __restrict__ h,
    const float* __restrict__ asrc, const float* __restrict__ adst,
    const float* __restrict__ bias,
    __nv_bfloat16* __restrict__ outh)
{
    const int H = HEADS, CH = 64;
    __shared__ int   s_src[CH];
    __shared__ float s_w[CH * H];
    __shared__ float s_f[H];
    __shared__ float s_den[H];
    __shared__ float s_comb[64][8];

    int node = blockIdx.x, t = threadIdx.x;
    int wid = t >> 5, lane = t & 31;
    int qw = t & 63;            // uint4 index within 1KB row
    int eo = t >> 6;            // edge parity group
    int hh = qw >> 4;           // head owning channels qw*8..qw*8+7
    int beg = g_rowbeg[node];
    int end = beg + g_deg[node];

    float acc[8];
#pragma unroll
    for (int j = 0; j < 8; j++) acc[j] = 0.f;
    float m = -1e30f, ssum = 0.f;
    float ad = adst[node * H + wid];

    for (int cbeg = beg; cbeg < end; cbeg += CH) {
        int clen = min(CH, end - cbeg);
        {
            float lmax = -1e30f;
            for (int i = lane; i < clen; i += 32) {
                int s = g_esrc[cbeg + i];
                if (wid == 0) s_src[i] = s;
                float l = asrc[s * H + wid] + ad;
                l = l > 0.f ? l : 0.2f * l;
                s_w[i * H + wid] = l;
                lmax = fmaxf(lmax, l);
            }
#pragma unroll
            for (int o = 16; o; o >>= 1)
                lmax = fmaxf(lmax, __shfl_xor_sync(0xffffffffu, lmax, o));
            float newm = fmaxf(m, lmax);
            float f = __expf(m - newm);
            m = newm;
            float lsum = 0.f;
            for (int i = lane; i < clen; i += 32) {
                float w = __expf(s_w[i * H + wid] - m);
                s_w[i * H + wid] = w;
                lsum += w;
            }
#pragma unroll
            for (int o = 16; o; o >>= 1)
                lsum += __shfl_xor_sync(0xffffffffu, lsum, o);
            ssum = ssum * f + lsum;
            if (lane == 0) s_f[wid] = f;
        }
        __syncthreads();
        float f = s_f[hh];
#pragma unroll
        for (int j = 0; j < 8; j++) acc[j] *= f;

        int i = eo;
        for (; i + 2 < clen; i += 4) {
            int s0 = s_src[i], s1 = s_src[i + 2];
            float w0 = s_w[i * H + hh], w1 = s_w[(i + 2) * H + hh];
            uint4 v0 = *reinterpret_cast<const uint4*>(h + (size_t)s0 * C1 + qw * 8);
            uint4 v1 = *reinterpret_cast<const uint4*>(h + (size_t)s1 * C1 + qw * 8);
            float2 a0 = __bfloat1622float2(*reinterpret_cast<__nv_bfloat162*>(&v0.x));
            float2 a1 = __bfloat1622float2(*reinterpret_cast<__nv_bfloat162*>(&v0.y));
            float2 a2 = __bfloat1622float2(*reinterpret_cast<__nv_bfloat162*>(&v0.z));
            float2 a3 = __bfloat1622float2(*reinterpret_cast<__nv_bfloat162*>(&v0.w));
            float2 b0 = __bfloat1622float2(*reinterpret_cast<__nv_bfloat162*>(&v1.x));
            float2 b1 = __bfloat1622float2(*reinterpret_cast<__nv_bfloat162*>(&v1.y));
            float2 b2 = __bfloat1622float2(*reinterpret_cast<__nv_bfloat162*>(&v1.z));
            float2 b3 = __bfloat1622float2(*reinterpret_cast<__nv_bfloat162*>(&v1.w));
            acc[0] += w0 * a0.x + w1 * b0.x;  acc[1] += w0 * a0.y + w1 * b0.y;
            acc[2] += w0 * a1.x + w1 * b1.x;  acc[3] += w0 * a1.y + w1 * b1.y;
            acc[4] += w0 * a2.x + w1 * b2.x;  acc[5] += w0 * a2.y + w1 * b2.y;
            acc[6] += w0 * a3.x + w1 * b3.x;  acc[7] += w0 * a3.y + w1 * b3.y;
        }
        for (; i < clen; i += 2) {
            int s = s_src[i];
            float w = s_w[i * H + hh];
            uint4 v = *reinterpret_cast<const uint4*>(h + (size_t)s * C1 + qw * 8);
            float2 a0 = __bfloat1622float2(*reinterpret_cast<__nv_bfloat162*>(&v.x));
            float2 a1 = __bfloat1622float2(*reinterpret_cast<__nv_bfloat162*>(&v.y));
            float2 a2 = __bfloat1622float2(*reinterpret_cast<__nv_bfloat162*>(&v.z));
            float2 a3 = __bfloat1622float2(*reinterpret_cast<__nv_bfloat162*>(&v.w));
            acc[0] += w * a0.x;  acc[1] += w * a0.y;
            acc[2] += w * a1.x;  acc[3] += w * a1.y;
            acc[4] += w * a2.x;  acc[5] += w * a2.y;
            acc[6] += w * a3.x;  acc[7] += w * a3.y;
        }
        __syncthreads();
    }
    if (lane == 0) s_den[wid] = ssum;
    if (eo == 1) {
#pragma unroll
        for (int j = 0; j < 8; j++) s_comb[qw][j] = acc[j];
    }
    __syncthreads();
    if (eo == 0) {
        float den = s_den[hh];
        int ch = qw * 8;
        __nv_bfloat16 o[8];
#pragma unroll
        for (int j = 0; j < 8; j++) {
            float v = (acc[j] + s_comb[qw][j]) / den + bias[ch + j];
            v = v > 0.f ? v : expm1f(v);
            o[j] = __float2bfloat16_rn(v);
        }
        *reinterpret_cast<uint4*>(&outh[(size_t)node * C1 + ch]) =
            *reinterpret_cast<uint4*>(o);
    }
}

// ---------------- agg layer 2: H=1, uint4 gather + fused mean-pool ---------
__global__ __launch_bounds__(128) void agg2_kernel(
    const __nv_bfloat16* __restrict__ h,
    const float* __restrict__ asrc, const float* __restrict__ adst,
    const float* __restrict__ bias, const int* __restrict__ batch)
{
    const int CH = 64;
    __shared__ int   s_src[CH];
    __shared__ float s_w[CH];
    __shared__ float s_fd[2];       // [0]=f, [1]=den
    __shared__ float s_comb[8][16][8];

    int node = blockIdx.x, t = threadIdx.x;
    int wid = t >> 5, lane = t & 31;
    int qw = t & 15;
    int eg = t >> 4;                // edge group 0..7
    int beg = g_rowbeg[node];
    int end = beg + g_deg[node];

    float acc[8];
#pragma unroll
    for (int j = 0; j < 8; j++) acc[j] = 0.f;
    float m = -1e30f, ssum = 0.f;
    float ad = adst[node];

    for (int cbeg = beg; cbeg < end; cbeg += CH) {
        int clen = min(CH, end - cbeg);
        if (wid == 0) {
            float lmax = -1e30f;
            for (int i = lane; i < clen; i += 32) {
                int s = g_esrc[cbeg + i];
                s_src[i] = s;
                float l = asrc[s] + ad;
                l = l > 0.f ? l : 0.2f * l;
                s_w[i] = l;
                lmax = fmaxf(lmax, l);
            }
#pragma unroll
            for (int o = 16; o; o >>= 1)
                lmax = fmaxf(lmax, __shfl_xor_sync(0xffffffffu, lmax, o));
            float newm = fmaxf(m, lmax);
            float f = __expf(m - newm);
            m = newm;
            float lsum = 0.f;
            for (int i = lane; i < clen; i += 32) {
                float w = __expf(s_w[i] - m);
                s_w[i] = w;
                lsum += w;
            }
#pragma unroll
            for (int o = 16; o; o >>= 1)
                lsum += __shfl_xor_sync(0xffffffffu, lsum, o);
            ssum = ssum * f + lsum;
            if (lane == 0) { s_fd[0] = f; s_fd[1] = ssum; }
        }
        __syncthreads();
        float f = s_fd[0];
#pragma unroll
        for (int j = 0; j < 8; j++) acc[j] *= f;

        for (int i = eg; i < clen; i += 8) {
            int s = s_src[i];
            float w = s_w[i];
            uint4 v = *reinterpret_cast<const uint4*>(h + (size_t)s * HIDC + qw * 8);
            float2 a0 = __bfloat1622float2(*reinterpret_cast<__nv_bfloat162*>(&v.x));
            float2 a1 = __bfloat1622float2(*reinterpret_cast<__nv_bfloat162*>(&v.y));
            float2 a2 = __bfloat1622float2(*reinterpret_cast<__nv_bfloat162*>(&v.z));
            float2 a3 = __bfloat1622float2(*reinterpret_cast<__nv_bfloat162*>(&v.w));
            acc[0] += w * a0.x;  acc[1] += w * a0.y;
            acc[2] += w * a1.x;  acc[3] += w * a1.y;
            acc[4] += w * a2.x;  acc[5] += w * a2.y;
            acc[6] += w * a3.x;  acc[7] += w * a3.y;
        }
        __syncthreads();
    }
#pragma unroll
    for (int j = 0; j < 8; j++) s_comb[eg][qw][j] = acc[j];
    __syncthreads();
    int g = batch[node];
    {
        float den = s_fd[1];
        float sum = 0.f;
#pragma unroll
        for (int gq = 0; gq < 8; gq++) sum += s_comb[gq][t >> 3][t & 7];
        float v = sum / den + bias[t];
        v = v > 0.f ? v : expm1f(v);
        atomicAdd(&g_pool[g * HIDC + t], v);
    }
    if (t == 0) atomicAdd(&g_cnt[g], 1.0f);
}

// ---------------- final linear head ----------------------------------------
__global__ void final_kernel(const float* __restrict__ Wl,
                             const float* __restrict__ bl,
                             float* __restrict__ out)
{
    __shared__ float s_red[4];
    int g = blockIdx.x, t = threadIdx.x;
    int lane = t & 31, w = t >> 5;
    float c = fmaxf(g_cnt[g], 1.0f);
    float v = g_pool[g * HIDC + t] / c * Wl[t];
#pragma unroll
    for (int o = 16; o; o >>= 1) v += __shfl_down_sync(0xffffffffu, v, o);
    if (lane == 0) s_red[w] = v;
    __syncthreads();
    if (t == 0) out[g] = s_red[0] + s_red[1] + s_red[2] + s_red[3] + bl[0];
}

// ---------------- launch ----------------------------------------------------
extern "C" void kernel_launch(void* const* d_in, const int* in_sizes, int n_in,
                              void* d_out, int out_size)
{
    const float* x       = (const float*)d_in[0];
    const int*   ei      = (const int*)  d_in[1];
    const int*   batch   = (const int*)  d_in[2];
    const float* W1      = (const float*)d_in[3];
    const float* a_src1  = (const float*)d_in[4];
    const float* a_dst1  = (const float*)d_in[5];
    const float* b1      = (const float*)d_in[6];
    const float* W2      = (const float*)d_in[7];
    const float* a_src2  = (const float*)d_in[8];
    const float* a_dst2  = (const float*)d_in[9];
    const float* b2      = (const float*)d_in[10];
    const float* Wl      = (const float*)d_in[11];
    const float* bl      = (const float*)d_in[12];
    float* out = (float*)d_out;

    float *p_asrc1, *p_adst1, *p_asrc2, *p_adst2;
    __nv_bfloat16 *p_h1b, *p_h2b, *p_xh, *p_a1h, *p_w1h, *p_w1l, *p_w2h, *p_w2l;
    cudaGetSymbolAddress((void**)&p_h1b,   g_h1b);
    cudaGetSymbolAddress((void**)&p_h2b,   g_h2b);
    cudaGetSymbolAddress((void**)&p_asrc1, g_asrc1);
    cudaGetSymbolAddress((void**)&p_adst1, g_adst1);
    cudaGetSymbolAddress((void**)&p_asrc2, g_asrc2);
    cudaGetSymbolAddress((void**)&p_adst2, g_adst2);
    cudaGetSymbolAddress((void**)&p_xh,  g_xh);
    cudaGetSymbolAddress((void**)&p_a1h, g_a1h);
    cudaGetSymbolAddress((void**)&p_w1h, g_w1h);
    cudaGetSymbolAddress((void**)&p_w1l, g_w1l);
    cudaGetSymbolAddress((void**)&p_w2h, g_w2h);
    cudaGetSymbolAddress((void**)&p_w2l, g_w2l);

    prep_kernel<<<1024, 256>>>(x, W1, W2);
    count_kernel<<<(EE + 255) / 256, 256>>>(ei);
    alloc_kernel<<<(NN + 255) / 256, 256>>>();
    scatter_kernel<<<(ET + 255) / 256, 256>>>(ei);

    // layer 1: h1 = x @ W1 (+ fused dots)
    {
        dim3 grid(C1 / 128, (NN + 127) / 128);
        mma_gemm_kernel<<<grid, 256>>>(p_xh, p_w1h, p_w1l, p_h1b,
                                       a_src1, a_dst1, p_asrc1, p_adst1,
                                       NN, C1, FIN, HEADS);
    }
    agg1_kernel<<<NN, 128>>>(p_h1b, p_asrc1, p_adst1, b1, p_a1h);

    // layer 2: h2 = act1 @ W2 (+ fused dots)
    {
        dim3 grid(HIDC / 128, (NN + 127) / 128);
        mma_gemm_kernel<<<grid, 256>>>(p_a1h, p_w2h, p_w2l, p_h2b,
                                       a_src2, a_dst2, p_asrc2, p_adst2,
                                       NN, HIDC, C1, 1);
    }
    // layer 2 agg + fused mean-pool
    agg2_kernel<<<NN, 128>>>(p_h2b, p_asrc2, p_adst2, b2, batch);

    final_kernel<<<GG, HIDC>>>(Wl, bl, out);
}